// round 2
// baseline (speedup 1.0000x reference)
#include <cuda_runtime.h>
#include <cstdint>
#include <cstring>
#include <vector>
#include <algorithm>

#define B_ROWS 16384
#define D_COLS 2048
#define NCLS   1000

// Scratch (device globals: allocation-free per harness rules)
__device__ unsigned short g_index[B_ROWS];          // permutation, host-computed
__device__ float g_cn[NCLS * D_COLS];               // class_noise matrix (8MB)

// ---------------------------------------------------------------------------
// JAX threefry2x32 (20 rounds), bit-exact. Host+device.
// ---------------------------------------------------------------------------
__host__ __device__ __forceinline__ void threefry2x32(
    uint32_t k0, uint32_t k1, uint32_t x0, uint32_t x1,
    uint32_t &o0, uint32_t &o1)
{
    uint32_t ks0 = k0, ks1 = k1, ks2 = k0 ^ k1 ^ 0x1BD11BDAu;
    x0 += ks0; x1 += ks1;
    const int R[2][4] = {{13, 15, 26, 6}, {17, 29, 16, 24}};
#pragma unroll
    for (int i = 0; i < 5; i++) {
#pragma unroll
        for (int j = 0; j < 4; j++) {
            int r = R[i & 1][j];
            x0 += x1;
            x1 = (x1 << r) | (x1 >> (32 - r));
            x1 ^= x0;
        }
        uint32_t a = (i + 1) % 3 == 0 ? ks0 : ((i + 1) % 3 == 1 ? ks1 : ks2);
        uint32_t b = (i + 2) % 3 == 0 ? ks0 : ((i + 2) % 3 == 1 ? ks1 : ks2);
        x0 += a;
        x1 += b + (uint32_t)(i + 1);
    }
    o0 = x0; o1 = x1;
}

// ---------------------------------------------------------------------------
// XLA f32 ErfInv (Giles polynomial) — matches lax.erf_inv to ulp-level
// ---------------------------------------------------------------------------
__device__ __forceinline__ float erfinv_f32(float x)
{
    float w = -log1pf(-x * x);
    float p;
    if (w < 5.0f) {
        w -= 2.5f;
        p = 2.81022636e-08f;
        p = fmaf(p, w, 3.43273939e-07f);
        p = fmaf(p, w, -3.5233877e-06f);
        p = fmaf(p, w, -4.39150654e-06f);
        p = fmaf(p, w, 0.00021858087f);
        p = fmaf(p, w, -0.00125372503f);
        p = fmaf(p, w, -0.00417768164f);
        p = fmaf(p, w, 0.246640727f);
        p = fmaf(p, w, 1.50140941f);
    } else {
        w = sqrtf(w) - 3.0f;
        p = -0.000200214257f;
        p = fmaf(p, w, 0.000100950558f);
        p = fmaf(p, w, 0.00134934322f);
        p = fmaf(p, w, -0.00367342844f);
        p = fmaf(p, w, 0.00573950773f);
        p = fmaf(p, w, -0.0076224613f);
        p = fmaf(p, w, 0.00943887047f);
        p = fmaf(p, w, 1.00167406f);
        p = fmaf(p, w, 2.83297682f);
    }
    return p * x;
}

// jax.random.normal sample at flat counter idx (partitionable threefry:
// bits = o0 ^ o1 of threefry(key, (0, idx)); uniform in [lo,1); sqrt2*erfinv)
__device__ __forceinline__ float jax_normal(uint32_t nk0, uint32_t nk1, uint32_t idx)
{
    uint32_t b0, b1;
    threefry2x32(nk0, nk1, 0u, idx, b0, b1);
    uint32_t bits = b0 ^ b1;
    float f = __uint_as_float((bits >> 9) | 0x3f800000u);   // [1,2)
    const float lo = -0.99999994039535522461f;               // nextafter(-1,0)
    float u = fmaxf(lo, fmaf(f - 1.0f, 2.0f, lo));           // hi-lo == 2.0f in f32
    return 1.41421356237309504880f * erfinv_f32(u);
}

__device__ __forceinline__ float cn_val(float s, float q, float cnt,
                                        uint32_t nk0, uint32_t nk1, uint32_t flat)
{
    float mean = s / cnt;
    float var  = (q - cnt * mean * mean) / (cnt - 1.0f);
    float sd   = sqrtf(fmaxf(var, 0.0f));
    return mean + sd * jax_normal(nk0, nk1, flat);
}

// ---------------------------------------------------------------------------
// Kernel 1: per-class stats fused with noise generation.
// One CTA per class: scan y, sort matching rows (deterministic FP order),
// accumulate sum/sumsq over D, write class_noise row.
// ---------------------------------------------------------------------------
__global__ __launch_bounds__(256) void stats_noise_kernel(
    const float* __restrict__ x, const int* __restrict__ y,
    uint32_t nk0, uint32_t nk1)
{
    __shared__ int rows[1024];
    __shared__ int rcnt;
    int c = blockIdx.x;
    int t = threadIdx.x;
    if (t == 0) rcnt = 0;
    __syncthreads();
    for (int i = t; i < B_ROWS; i += 256) {
        if (y[i] == c) {
            int p = atomicAdd(&rcnt, 1);
            if (p < 1024) rows[p] = i;
        }
    }
    __syncthreads();
    int n = min(rcnt, 1024);
    if (t == 0) {   // insertion sort (~16 elems) for deterministic sum order
        for (int a = 1; a < n; a++) {
            int v = rows[a]; int b = a - 1;
            while (b >= 0 && rows[b] > v) { rows[b + 1] = rows[b]; b--; }
            rows[b + 1] = v;
        }
    }
    __syncthreads();

    float4 s0 = {0,0,0,0}, s1 = {0,0,0,0}, q0 = {0,0,0,0}, q1 = {0,0,0,0};
    for (int r = 0; r < n; r++) {
        const float4* xr = reinterpret_cast<const float4*>(x) + (size_t)rows[r] * 512;
        float4 v = xr[t];
        s0.x += v.x; s0.y += v.y; s0.z += v.z; s0.w += v.w;
        q0.x += v.x*v.x; q0.y += v.y*v.y; q0.z += v.z*v.z; q0.w += v.w*v.w;
        float4 w = xr[t + 256];
        s1.x += w.x; s1.y += w.y; s1.z += w.z; s1.w += w.w;
        q1.x += w.x*w.x; q1.y += w.y*w.y; q1.z += w.z*w.z; q1.w += w.w*w.w;
    }
    float cnt = (float)n;
    uint32_t base = (uint32_t)c * (uint32_t)D_COLS;
    uint32_t d0 = base + (uint32_t)t * 4u;
    uint32_t d1 = base + 1024u + (uint32_t)t * 4u;
    float4 o0, o1;
    o0.x = cn_val(s0.x, q0.x, cnt, nk0, nk1, d0 + 0u);
    o0.y = cn_val(s0.y, q0.y, cnt, nk0, nk1, d0 + 1u);
    o0.z = cn_val(s0.z, q0.z, cnt, nk0, nk1, d0 + 2u);
    o0.w = cn_val(s0.w, q0.w, cnt, nk0, nk1, d0 + 3u);
    o1.x = cn_val(s1.x, q1.x, cnt, nk0, nk1, d1 + 0u);
    o1.y = cn_val(s1.y, q1.y, cnt, nk0, nk1, d1 + 1u);
    o1.z = cn_val(s1.z, q1.z, cnt, nk0, nk1, d1 + 2u);
    o1.w = cn_val(s1.w, q1.w, cnt, nk0, nk1, d1 + 3u);
    float4* cn4 = reinterpret_cast<float4*>(g_cn);
    cn4[(size_t)c * 512 + t]       = o0;
    cn4[(size_t)c * 512 + 256 + t] = o1;
}

// ---------------------------------------------------------------------------
// Kernel 2: out = 0.9*x + 0.1*cn[newY[row]], newY[row] = y[perm[row]]
// ---------------------------------------------------------------------------
__global__ __launch_bounds__(256) void out_kernel(
    const float* __restrict__ x, const int* __restrict__ y,
    float* __restrict__ out, int out_size)
{
    int row = blockIdx.x;
    int t = threadIdx.x;
    int c = __ldg(&y[g_index[row]]);
    const float4* x4 = reinterpret_cast<const float4*>(x) + (size_t)row * 512;
    const float4* n4 = reinterpret_cast<const float4*>(g_cn) + (size_t)c * 512;
    float4* o4 = reinterpret_cast<float4*>(out) + (size_t)row * 512;

    float4 a = x4[t], b = n4[t], o;
    o.x = 0.9f * a.x + 0.1f * b.x;
    o.y = 0.9f * a.y + 0.1f * b.y;
    o.z = 0.9f * a.z + 0.1f * b.z;
    o.w = 0.9f * a.w + 0.1f * b.w;
    o4[t] = o;
    a = x4[t + 256]; b = n4[t + 256];
    o.x = 0.9f * a.x + 0.1f * b.x;
    o.y = 0.9f * a.y + 0.1f * b.y;
    o.z = 0.9f * a.z + 0.1f * b.z;
    o.w = 0.9f * a.w + 0.1f * b.w;
    o4[t + 256] = o;

    if (t == 0) {
        long long p = (long long)B_ROWS * D_COLS + row;
        if (p < (long long)out_size) out[p] = (float)c;   // newY as numeric value
    }
}

// ---------------------------------------------------------------------------
// Permutation upload via kernel parameters (no memcpy nodes needed).
// 16384 u16 split into two 16KB param structs (< 32764B param limit).
// ---------------------------------------------------------------------------
struct IdxChunk { unsigned short v[8192]; };

__global__ void upload_idx_kernel(IdxChunk ch, int off)
{
    int t = blockIdx.x * blockDim.x + threadIdx.x;
    if (t < 8192) g_index[off + t] = ch.v[t];
}

// ---------------------------------------------------------------------------
// Host: replicate jax.random key derivation + permutation.
// jax.random.permutation(pk, 16384) -> _shuffle with
//   num_rounds = ceil(3*ln(16384)/ln(2^32-1)) = 2  stable sort rounds.
// Pure constants (input-independent) -> computed on host, embedded as params.
// ---------------------------------------------------------------------------
extern "C" void kernel_launch(void* const* d_in, const int* in_sizes, int n_in,
                              void* d_out, int out_size)
{
    const float* x = (const float*)d_in[0];
    const int*   y = (const int*)d_in[1];
    float* out = (float*)d_out;

    // nk, pk = split(key(42))  [partitionable/fold-like: counters (0,0),(0,1)]
    uint32_t nk0, nk1, pk0, pk1;
    threefry2x32(0u, 42u, 0u, 0u, nk0, nk1);
    threefry2x32(0u, 42u, 0u, 1u, pk0, pk1);

    // permutation(pk, 16384): 2 rounds of (split; random_bits; stable sort_key_val)
    std::vector<uint16_t> perm(B_ROWS), tmp(B_ROWS);
    std::vector<uint64_t> buf(B_ROWS);
    for (int i = 0; i < B_ROWS; i++) perm[i] = (uint16_t)i;
    uint32_t k0 = pk0, k1 = pk1;
    const int NUM_ROUNDS = 2;   // ceil(3*log(16384)/log(2^32-1))
    for (int r = 0; r < NUM_ROUNDS; r++) {
        uint32_t t0, t1, s0, s1;
        threefry2x32(k0, k1, 0u, 0u, t0, t1);   // next chain key  (split[0])
        threefry2x32(k0, k1, 0u, 1u, s0, s1);   // subkey          (split[1])
        k0 = t0; k1 = t1;
        for (int i = 0; i < B_ROWS; i++) {
            uint32_t b0, b1;
            threefry2x32(s0, s1, 0u, (uint32_t)i, b0, b1);
            buf[i] = ((uint64_t)(b0 ^ b1) << 32) | (uint32_t)i;  // stable: pos tiebreak
        }
        std::sort(buf.begin(), buf.end());
        for (int j = 0; j < B_ROWS; j++)
            tmp[j] = perm[(uint32_t)(buf[j] & 0xFFFFFFFFu)];
        perm.swap(tmp);
    }

    IdxChunk c0, c1;
    memcpy(c0.v, perm.data(),        8192 * sizeof(uint16_t));
    memcpy(c1.v, perm.data() + 8192, 8192 * sizeof(uint16_t));
    upload_idx_kernel<<<32, 256>>>(c0, 0);
    upload_idx_kernel<<<32, 256>>>(c1, 8192);

    stats_noise_kernel<<<NCLS, 256>>>(x, y, nk0, nk1);
    out_kernel<<<B_ROWS, 256>>>(x, y, out, out_size);
}